// round 8
// baseline (speedup 1.0000x reference)
#include <cuda_runtime.h>
#include <math_constants.h>

#define N_MAX 30000
#define M_MAX 10000
#define G     32
#define NC    (G * G * G)          // 32768 cells per grid
#define NCT   (2 * NC)             // grid 0: Ps (targets for A); grid 1: P (targets for B)
#define LHALF 4.0f                 // domain [-4, 4]^3 (coords clamped into edge cells)
#define CELLH 0.25f                // 8 / 32
#define INVH  4.0f

// Device scratch (zero-init at load; self-cleaning across graph replays).
__device__ unsigned int g_counts[NCT];          // zeroed by scan_kernel after use
__device__ uint2        g_range[NCT];           // [start, end) slot range per cell
__device__ unsigned int g_cursor[NCT];
__device__ float4       g_sp[N_MAX + M_MAX];    // sorted points, .w = orig index bits
__device__ float        g_term[N_MAX + M_MAX];  // per-point loss terms
#define NB_RED 40
__device__ float g_partials[NB_RED];
__device__ int   g_done = 0;                    // arrival counter; self-resets

// ---------------------------------------------------------------------------
__device__ __forceinline__ int cellCoord(float x) {
    int c = (int)floorf((x + LHALF) * INVH);
    return min(max(c, 0), G - 1);
}
__device__ __forceinline__ int cellOf(float x, float y, float z) {
    return (cellCoord(z) * G + cellCoord(y)) * G + cellCoord(x);
}

// ---------------------------------------------------------------------------
// 1) count points per cell (both grids)
// ---------------------------------------------------------------------------
__global__ void count_kernel(const float* __restrict__ P,
                             const float* __restrict__ Ps, int n, int m) {
    int i = blockIdx.x * blockDim.x + threadIdx.x;
    if (i < m) {
        const float* q = Ps + 3 * i;
        atomicAdd(&g_counts[cellOf(q[0], q[1], q[2])], 1u);
    } else if (i < m + n) {
        const float* p = P + 3 * (i - m);
        atomicAdd(&g_counts[NC + cellOf(p[0], p[1], p[2])], 1u);
    }
}

// ---------------------------------------------------------------------------
// 2) exclusive prefix over all cells (1 block); writes ranges+cursors, zeroes
//    counts for the next graph replay.
// ---------------------------------------------------------------------------
#define SCAN_T 1024
#define CPT    (NCT / SCAN_T)      // 64 cells per thread
__global__ __launch_bounds__(SCAN_T) void scan_kernel() {
    __shared__ unsigned int ssum[SCAN_T];
    const int t = threadIdx.x;
    const int c0 = t * CPT;

    unsigned int s = 0;
    for (int c = c0; c < c0 + CPT; c++) s += g_counts[c];
    ssum[t] = s;
    __syncthreads();

    // Hillis–Steele inclusive scan
    for (int off = 1; off < SCAN_T; off <<= 1) {
        unsigned int v = (t >= off) ? ssum[t - off] : 0u;
        __syncthreads();
        ssum[t] += v;
        __syncthreads();
    }
    unsigned int base = (t == 0) ? 0u : ssum[t - 1];

    for (int c = c0; c < c0 + CPT; c++) {
        unsigned int cnt = g_counts[c];
        g_range[c] = make_uint2(base, base + cnt);
        g_cursor[c] = base;
        g_counts[c] = 0u;          // clean for next replay
        base += cnt;
    }
}

// ---------------------------------------------------------------------------
// 3) scatter points into sorted slots (order nondeterministic; consumers are
//    order-invariant: u64 (d2,idx) min and per-slot term writes).
// ---------------------------------------------------------------------------
__global__ void scatter_kernel(const float* __restrict__ P,
                               const float* __restrict__ Ps, int n, int m) {
    int i = blockIdx.x * blockDim.x + threadIdx.x;
    if (i < m) {
        float x = Ps[3 * i], y = Ps[3 * i + 1], z = Ps[3 * i + 2];
        unsigned int slot = atomicAdd(&g_cursor[cellOf(x, y, z)], 1u);
        g_sp[slot] = make_float4(x, y, z, __uint_as_float((unsigned int)i));
    } else if (i < m + n) {
        int j = i - m;
        float x = P[3 * j], y = P[3 * j + 1], z = P[3 * j + 2];
        unsigned int slot = atomicAdd(&g_cursor[NC + cellOf(x, y, z)], 1u);
        g_sp[slot] = make_float4(x, y, z, __uint_as_float((unsigned int)j));
    }
}

// ---------------------------------------------------------------------------
// 4) nearest-neighbor query, one thread per (sorted) point.
//    Slots [0, m) are sorted Ps -> B-queries (search P-grid, base NC).
//    Slots [m, m+n) are sorted P -> A-queries (search Ps-grid, base 0).
//    Ring search with row-run merging (x-contiguous cells share contiguous
//    slot ranges).  Stop when ((s-1)*h)^2 (with safety factor) > best_d2.
// ---------------------------------------------------------------------------
__global__ __launch_bounds__(128)
void query_kernel(const float* __restrict__ prob, int n, int m) {
    const int u = blockIdx.x * blockDim.x + threadIdx.x;
    if (u >= n + m) return;

    const float4 q = g_sp[u];
    const bool isB = (u < m);
    const int cbase = isB ? NC : 0;

    const int cx = cellCoord(q.x), cy = cellCoord(q.y), cz = cellCoord(q.z);

    unsigned long long best = 0xFFFFFFFFFFFFFFFFull;   // (d2_bits<<32)|idx
    float bestd2 = CUDART_INF_F;

    for (int s = 0; s < G; s++) {
        if (s >= 2) {
            float b = (float)(s - 1) * CELLH * 0.999f;
            if (b * b > bestd2) break;
        }
        const int z0 = max(cz - s, 0), z1 = min(cz + s, G - 1);
        const int y0 = max(cy - s, 0), y1 = min(cy + s, G - 1);
        const int x0 = max(cx - s, 0), x1 = min(cx + s, G - 1);

        for (int iz = z0; iz <= z1; iz++) {
            const int adz = abs(iz - cz);
            for (int iy = y0; iy <= y1; iy++) {
                const int ady = max(adz, abs(iy - cy));
                if (ady > s) continue;          // (never true, bounds clipped)

                unsigned int v0, v1;            // merged candidate slot range(s)
                unsigned int w0 = 1, w1 = 0;    // optional second range (empty)
                const int rowb = cbase + (iz * G + iy) * G;
                if (ady == s) {
                    // whole x-run is on the ring: one contiguous slot range
                    v0 = g_range[rowb + x0].x;
                    v1 = g_range[rowb + x1].y;
                } else {
                    // only x = cx-s and cx+s are on the ring
                    v0 = 1; v1 = 0;
                    if (cx - s >= 0) {
                        uint2 r = g_range[rowb + cx - s];
                        v0 = r.x; v1 = r.y;
                    }
                    if (cx + s <= G - 1) {
                        uint2 r = g_range[rowb + cx + s];
                        w0 = r.x; w1 = r.y;
                    }
                }
                for (int half = 0; half < 2; half++) {
                    unsigned int a = half ? w0 : v0;
                    unsigned int b2 = half ? w1 : v1;
                    for (unsigned int v = a; v < b2; v++) {
                        float4 t = g_sp[v];
                        float dx = q.x - t.x;
                        float dy = q.y - t.y;
                        float dz = q.z - t.z;
                        float d2 = fmaf(dx, dx, fmaf(dy, dy, dz * dz));
                        unsigned long long pk =
                            ((unsigned long long)__float_as_uint(d2) << 32) |
                            (unsigned long long)__float_as_uint(t.w);
                        if (pk < best) best = pk;
                    }
                }
            }
        }
        bestd2 = __uint_as_float((unsigned int)(best >> 32));
    }

    const float d = sqrtf(__uint_as_float((unsigned int)(best >> 32)));
    const unsigned int widx = (unsigned int)(best & 0xFFFFFFFFu);
    const unsigned int qorig = __float_as_uint(q.w);
    if (isB) {
        g_term[qorig] = d * __ldg(&prob[qorig]);          // s->o term
    } else {
        g_term[m + qorig] = d * __ldg(&prob[widx]);       // o->s term
    }
}

// ---------------------------------------------------------------------------
// 5) deterministic sum of the n+m terms + fused final (arrival counter).
// ---------------------------------------------------------------------------
__global__ __launch_bounds__(256)
void reduce_kernel(int total, float* __restrict__ out) {
    __shared__ float ssum[256];
    __shared__ bool isLast;
    const int stride = gridDim.x * blockDim.x;

    float sum = 0.0f;
    for (int i = blockIdx.x * blockDim.x + threadIdx.x; i < total; i += stride)
        sum += g_term[i];

    ssum[threadIdx.x] = sum;
    __syncthreads();
    for (int off = 128; off > 0; off >>= 1) {
        if (threadIdx.x < off) ssum[threadIdx.x] += ssum[threadIdx.x + off];
        __syncthreads();
    }
    if (threadIdx.x == 0) {
        g_partials[blockIdx.x] = ssum[0];
        __threadfence();
        int t = atomicAdd(&g_done, 1);
        isLast = (t == (int)gridDim.x - 1);
    }
    __syncthreads();

    if (isLast) {
        __threadfence();
        volatile float* gp = g_partials;
        float v = (threadIdx.x < (int)gridDim.x) ? gp[threadIdx.x] : 0.0f;
        ssum[threadIdx.x] = v;
        __syncthreads();
        for (int off = 128; off > 0; off >>= 1) {
            if (threadIdx.x < off) ssum[threadIdx.x] += ssum[threadIdx.x + off];
            __syncthreads();
        }
        if (threadIdx.x == 0) {
            out[0] = ssum[0];
            g_done = 0;
        }
    }
}

// ---------------------------------------------------------------------------
// Launch: 5 kernels.
// ---------------------------------------------------------------------------
extern "C" void kernel_launch(void* const* d_in, const int* in_sizes, int n_in,
                              void* d_out, int out_size) {
    const float* P    = (const float*)d_in[0];
    const float* Ps   = (const float*)d_in[1];
    const float* prob = (const float*)d_in[2];
    float* out = (float*)d_out;

    const int n = in_sizes[0] / 3;   // 30000
    const int m = in_sizes[1] / 3;   // 10000
    const int total = n + m;
    const int nb = (total + 255) / 256;

    count_kernel<<<nb, 256>>>(P, Ps, n, m);
    scan_kernel<<<1, SCAN_T>>>();
    scatter_kernel<<<nb, 256>>>(P, Ps, n, m);
    query_kernel<<<(total + 127) / 128, 128>>>(prob, n, m);
    reduce_kernel<<<NB_RED, 256>>>(total, out);
}

// round 10
// speedup vs baseline: 2.8641x; 2.8641x over previous
#include <cuda_runtime.h>
#include <math_constants.h>

#define N_MAX 30000
#define M_MAX 10000
#define G     16
#define NC    (G * G * G)          // 4096 cells per grid
#define NCT   (2 * NC)             // grid 0: Ps (A targets); grid 1: P (B targets)
#define LHALF 4.0f                 // domain [-4, 4]^3 (coords clamped into edge cells)
#define CELLH 0.5f
#define INVH  2.0f

// Device scratch (zero-init at load; self-cleaning across graph replays).
__device__ unsigned int g_counts[NCT];          // zeroed by scan_kernel after use
__device__ uint2        g_range[NCT];           // [start, end) slot range per cell
__device__ unsigned int g_cursor[NCT];
__device__ float4       g_sp[N_MAX + M_MAX];    // sorted points, .w = orig index bits
__device__ float        g_term[N_MAX + M_MAX];  // per-point loss terms
#define NB_RED 40
__device__ float g_partials[NB_RED];
__device__ int   g_done = 0;                    // arrival counter; self-resets

// ---------------------------------------------------------------------------
__device__ __forceinline__ int cellCoord(float x) {
    int c = (int)floorf((x + LHALF) * INVH);
    return min(max(c, 0), G - 1);
}
__device__ __forceinline__ int cellOf(float x, float y, float z) {
    return (cellCoord(z) * G + cellCoord(y)) * G + cellCoord(x);
}

// ---------------------------------------------------------------------------
// 1) count points per cell (both grids)
// ---------------------------------------------------------------------------
__global__ void count_kernel(const float* __restrict__ P,
                             const float* __restrict__ Ps, int n, int m) {
    int i = blockIdx.x * blockDim.x + threadIdx.x;
    if (i < m) {
        const float* q = Ps + 3 * i;
        atomicAdd(&g_counts[cellOf(q[0], q[1], q[2])], 1u);
    } else if (i < m + n) {
        const float* p = P + 3 * (i - m);
        atomicAdd(&g_counts[NC + cellOf(p[0], p[1], p[2])], 1u);
    }
}

// ---------------------------------------------------------------------------
// 2) exclusive prefix over all 8192 cells (1 block, 8 cells/thread);
//    writes ranges+cursors, zeroes counts for the next replay.
// ---------------------------------------------------------------------------
#define SCAN_T 1024
#define CPT    (NCT / SCAN_T)      // 8 cells per thread
__global__ __launch_bounds__(SCAN_T) void scan_kernel() {
    __shared__ unsigned int ssum[SCAN_T];
    const int t = threadIdx.x;
    const int c0 = t * CPT;

    unsigned int s = 0;
    #pragma unroll
    for (int c = 0; c < CPT; c++) s += g_counts[c0 + c];
    ssum[t] = s;
    __syncthreads();

    for (int off = 1; off < SCAN_T; off <<= 1) {
        unsigned int v = (t >= off) ? ssum[t - off] : 0u;
        __syncthreads();
        ssum[t] += v;
        __syncthreads();
    }
    unsigned int base = (t == 0) ? 0u : ssum[t - 1];

    #pragma unroll
    for (int c = 0; c < CPT; c++) {
        unsigned int cnt = g_counts[c0 + c];
        g_range[c0 + c] = make_uint2(base, base + cnt);
        g_cursor[c0 + c] = base;
        g_counts[c0 + c] = 0u;     // clean for next replay
        base += cnt;
    }
}

// ---------------------------------------------------------------------------
// 3) scatter points into sorted slots (order nondeterministic; consumers are
//    order-invariant: exact u64 (d2,idx) mins and per-slot writes).
// ---------------------------------------------------------------------------
__global__ void scatter_kernel(const float* __restrict__ P,
                               const float* __restrict__ Ps, int n, int m) {
    int i = blockIdx.x * blockDim.x + threadIdx.x;
    if (i < m) {
        float x = Ps[3 * i], y = Ps[3 * i + 1], z = Ps[3 * i + 2];
        unsigned int slot = atomicAdd(&g_cursor[cellOf(x, y, z)], 1u);
        g_sp[slot] = make_float4(x, y, z, __uint_as_float((unsigned int)i));
    } else if (i < m + n) {
        int j = i - m;
        float x = P[3 * j], y = P[3 * j + 1], z = P[3 * j + 2];
        unsigned int slot = atomicAdd(&g_cursor[NC + cellOf(x, y, z)], 1u);
        g_sp[slot] = make_float4(x, y, z, __uint_as_float((unsigned int)j));
    }
}

// ---------------------------------------------------------------------------
// 4) nearest-neighbor query: ONE WARP PER QUERY.
//    Lanes stride over the ring's cells; per-lane packed (d2,idx) best;
//    warp-wide u64 min reduction once per ring (s>=1).
//    Ring bound: d >= (s-1)*h - o, where o = query's overflow beyond the
//    clamped domain (clamped queries aren't inside their cell; subtracting o
//    restores a valid lower bound).
// ---------------------------------------------------------------------------
__global__ __launch_bounds__(256)
void query_kernel(const float* __restrict__ prob, int n, int m) {
    const int w = (blockIdx.x * blockDim.x + threadIdx.x) >> 5;
    const int lane = threadIdx.x & 31;
    const int total = n + m;
    if (w >= total) return;

    const float4 q = g_sp[w];
    const bool isB = (w < m);
    const int cbase = isB ? NC : 0;

    const int cx = cellCoord(q.x), cy = cellCoord(q.y), cz = cellCoord(q.z);
    const float o = fmaxf(fmaxf(fabsf(q.x), fmaxf(fabsf(q.y), fabsf(q.z))) - LHALF, 0.0f);

    unsigned long long best = 0xFFFFFFFFFFFFFFFFull;   // (d2_bits<<32)|idx
    float bestd2 = CUDART_INF_F;

    for (int s = 0; s < G; s++) {
        if (s >= 2) {
            float b = (float)(s - 1) * CELLH * 0.999f - o;
            if (b > 0.0f && b * b > bestd2) break;
        }
        const int side = 2 * s + 1;
        const int box = side * side * side;

        for (int t = lane; t < box; t += 32) {
            int dz = t / (side * side);
            int rem = t - dz * side * side;
            int dy = rem / side;
            int dx = rem - dy * side;
            dz -= s; dy -= s; dx -= s;
            if (max(abs(dx), max(abs(dy), abs(dz))) != s) continue;   // ring shell only
            const int ix = cx + dx, iy = cy + dy, iz = cz + dz;
            if (ix < 0 || ix >= G || iy < 0 || iy >= G || iz < 0 || iz >= G) continue;
            const uint2 r = g_range[cbase + (iz * G + iy) * G + ix];
            for (unsigned int v = r.x; v < r.y; v++) {
                const float4 tp = g_sp[v];
                float ddx = q.x - tp.x;
                float ddy = q.y - tp.y;
                float ddz = q.z - tp.z;
                float d2 = fmaf(ddx, ddx, fmaf(ddy, ddy, ddz * ddz));
                unsigned long long pk =
                    ((unsigned long long)__float_as_uint(d2) << 32) |
                    (unsigned long long)__float_as_uint(tp.w);
                if (pk < best) best = pk;
            }
        }

        if (s >= 1) {
            // warp all-reduce min (exact, order-independent)
            #pragma unroll
            for (int off = 16; off > 0; off >>= 1) {
                unsigned long long ob = __shfl_xor_sync(0xFFFFFFFFu, best, off);
                if (ob < best) best = ob;
            }
            bestd2 = __uint_as_float((unsigned int)(best >> 32));
        }
    }

    if (lane == 0) {
        const float d = sqrtf(__uint_as_float((unsigned int)(best >> 32)));
        const unsigned int widx = (unsigned int)(best & 0xFFFFFFFFu);
        const unsigned int qorig = __float_as_uint(q.w);
        if (isB) {
            g_term[qorig] = d * __ldg(&prob[qorig]);      // s->o term
        } else {
            g_term[m + qorig] = d * __ldg(&prob[widx]);   // o->s term
        }
    }
}

// ---------------------------------------------------------------------------
// 5) deterministic fixed-order sum of n+m terms + fused final.
// ---------------------------------------------------------------------------
__global__ __launch_bounds__(256)
void reduce_kernel(int total, float* __restrict__ out) {
    __shared__ float ssum[256];
    __shared__ bool isLast;
    const int stride = gridDim.x * blockDim.x;

    float sum = 0.0f;
    for (int i = blockIdx.x * blockDim.x + threadIdx.x; i < total; i += stride)
        sum += g_term[i];

    ssum[threadIdx.x] = sum;
    __syncthreads();
    for (int off = 128; off > 0; off >>= 1) {
        if (threadIdx.x < off) ssum[threadIdx.x] += ssum[threadIdx.x + off];
        __syncthreads();
    }
    if (threadIdx.x == 0) {
        g_partials[blockIdx.x] = ssum[0];
        __threadfence();
        int t = atomicAdd(&g_done, 1);
        isLast = (t == (int)gridDim.x - 1);
    }
    __syncthreads();

    if (isLast) {
        __threadfence();
        volatile float* gp = g_partials;
        float v = (threadIdx.x < (int)gridDim.x) ? gp[threadIdx.x] : 0.0f;
        ssum[threadIdx.x] = v;
        __syncthreads();
        for (int off = 128; off > 0; off >>= 1) {
            if (threadIdx.x < off) ssum[threadIdx.x] += ssum[threadIdx.x + off];
            __syncthreads();
        }
        if (threadIdx.x == 0) {
            out[0] = ssum[0];
            g_done = 0;
        }
    }
}

// ---------------------------------------------------------------------------
// Launch: 5 kernels.
// ---------------------------------------------------------------------------
extern "C" void kernel_launch(void* const* d_in, const int* in_sizes, int n_in,
                              void* d_out, int out_size) {
    const float* P    = (const float*)d_in[0];
    const float* Ps   = (const float*)d_in[1];
    const float* prob = (const float*)d_in[2];
    float* out = (float*)d_out;

    const int n = in_sizes[0] / 3;   // 30000
    const int m = in_sizes[1] / 3;   // 10000
    const int total = n + m;
    const int nb = (total + 255) / 256;

    count_kernel<<<nb, 256>>>(P, Ps, n, m);
    scan_kernel<<<1, SCAN_T>>>();
    scatter_kernel<<<nb, 256>>>(P, Ps, n, m);
    query_kernel<<<(total * 32 + 255) / 256, 256>>>(prob, n, m);
    reduce_kernel<<<NB_RED, 256>>>(total, out);
}

// round 11
// speedup vs baseline: 4.5432x; 1.5862x over previous
#include <cuda_runtime.h>
#include <math_constants.h>

#define N_MAX 30000
#define M_MAX 10000
#define G     16
#define NC    (G * G * G)          // 4096 cells per grid
#define NCT   (2 * NC)             // grid 0: Ps (A targets); grid 1: P (B targets)
#define LHALF 4.0f                 // domain [-4, 4]^3 (coords clamped into edge cells)
#define CELLH 0.5f
#define INVH  2.0f

// Device scratch (zero-init at load; self-cleaning across graph replays).
__device__ unsigned int g_counts[NCT];          // zeroed by scan_kernel after use
__device__ uint2        g_range[NCT];           // [start, end) slot range per cell
__device__ unsigned int g_cursor[NCT];
__device__ float4       g_sp[N_MAX + M_MAX];    // sorted points, .w = orig index bits
__device__ float        g_term[N_MAX + M_MAX];  // per-point loss terms
#define NB_RED 40
__device__ float g_partials[NB_RED];
__device__ int   g_done = 0;                    // arrival counter; self-resets

// ---------------------------------------------------------------------------
__device__ __forceinline__ int cellCoord(float x) {
    int c = (int)floorf((x + LHALF) * INVH);
    return min(max(c, 0), G - 1);
}
__device__ __forceinline__ int cellOf(float x, float y, float z) {
    return (cellCoord(z) * G + cellCoord(y)) * G + cellCoord(x);
}

// ---------------------------------------------------------------------------
// 1) count points per cell (both grids)
// ---------------------------------------------------------------------------
__global__ void count_kernel(const float* __restrict__ P,
                             const float* __restrict__ Ps, int n, int m) {
    int i = blockIdx.x * blockDim.x + threadIdx.x;
    if (i < m) {
        const float* q = Ps + 3 * i;
        atomicAdd(&g_counts[cellOf(q[0], q[1], q[2])], 1u);
    } else if (i < m + n) {
        const float* p = P + 3 * (i - m);
        atomicAdd(&g_counts[NC + cellOf(p[0], p[1], p[2])], 1u);
    }
}

// ---------------------------------------------------------------------------
// 2) exclusive prefix over all 8192 cells (1 block, 8 cells/thread);
//    writes ranges+cursors, zeroes counts for the next replay.
// ---------------------------------------------------------------------------
#define SCAN_T 1024
#define CPT    (NCT / SCAN_T)      // 8 cells per thread
__global__ __launch_bounds__(SCAN_T) void scan_kernel() {
    __shared__ unsigned int ssum[SCAN_T];
    const int t = threadIdx.x;
    const int c0 = t * CPT;

    unsigned int s = 0;
    #pragma unroll
    for (int c = 0; c < CPT; c++) s += g_counts[c0 + c];
    ssum[t] = s;
    __syncthreads();

    for (int off = 1; off < SCAN_T; off <<= 1) {
        unsigned int v = (t >= off) ? ssum[t - off] : 0u;
        __syncthreads();
        ssum[t] += v;
        __syncthreads();
    }
    unsigned int base = (t == 0) ? 0u : ssum[t - 1];

    #pragma unroll
    for (int c = 0; c < CPT; c++) {
        unsigned int cnt = g_counts[c0 + c];
        g_range[c0 + c] = make_uint2(base, base + cnt);
        g_cursor[c0 + c] = base;
        g_counts[c0 + c] = 0u;     // clean for next replay
        base += cnt;
    }
}

// ---------------------------------------------------------------------------
// 3) scatter points into sorted slots (order nondeterministic; consumers are
//    order-invariant: exact u64 (d2,idx) mins and per-slot writes).
// ---------------------------------------------------------------------------
__global__ void scatter_kernel(const float* __restrict__ P,
                               const float* __restrict__ Ps, int n, int m) {
    int i = blockIdx.x * blockDim.x + threadIdx.x;
    if (i < m) {
        float x = Ps[3 * i], y = Ps[3 * i + 1], z = Ps[3 * i + 2];
        unsigned int slot = atomicAdd(&g_cursor[cellOf(x, y, z)], 1u);
        g_sp[slot] = make_float4(x, y, z, __uint_as_float((unsigned int)i));
    } else if (i < m + n) {
        int j = i - m;
        float x = P[3 * j], y = P[3 * j + 1], z = P[3 * j + 2];
        unsigned int slot = atomicAdd(&g_cursor[NC + cellOf(x, y, z)], 1u);
        g_sp[slot] = make_float4(x, y, z, __uint_as_float((unsigned int)j));
    }
}

// ---------------------------------------------------------------------------
// 4) nearest-neighbor query: ONE WARP PER QUERY, candidate-parallel lanes.
//    Phase 1: 3x3x3 box = 9 contiguous row-runs; lanes stride candidates
//             within each run -> coalesced LDG.128 of g_sp.
//    Phase 2: rings s>=2 (rare), cell-per-lane shell enumeration.
//    Ring bound: d >= (s-1)*h - o  (o = query overflow beyond clamped domain).
// ---------------------------------------------------------------------------
__global__ __launch_bounds__(256)
void query_kernel(const float* __restrict__ prob, int n, int m) {
    const int w = (blockIdx.x * blockDim.x + threadIdx.x) >> 5;
    const int lane = threadIdx.x & 31;
    const int total = n + m;
    if (w >= total) return;

    const float4 q = g_sp[w];
    const bool isB = (w < m);
    const int cbase = isB ? NC : 0;

    const int cx = cellCoord(q.x), cy = cellCoord(q.y), cz = cellCoord(q.z);
    const float o = fmaxf(fmaxf(fabsf(q.x), fmaxf(fabsf(q.y), fabsf(q.z))) - LHALF, 0.0f);

    unsigned long long best = 0xFFFFFFFFFFFFFFFFull;   // (d2_bits<<32)|idx

    // ---- Phase 1: 3x3x3 box, rows of contiguous slots, lanes over candidates
    {
        const int x0 = max(cx - 1, 0), x1 = min(cx + 1, G - 1);
        const int y0 = max(cy - 1, 0), y1 = min(cy + 1, G - 1);
        const int z0 = max(cz - 1, 0), z1 = min(cz + 1, G - 1);

        for (int iz = z0; iz <= z1; iz++) {
            for (int iy = y0; iy <= y1; iy++) {
                const int rowb = cbase + (iz * G + iy) * G;
                const unsigned int r0 = g_range[rowb + x0].x;
                const unsigned int r1 = g_range[rowb + x1].y;
                for (unsigned int v = r0 + lane; v < r1; v += 32) {
                    const float4 tp = g_sp[v];      // coalesced across lanes
                    float ddx = q.x - tp.x;
                    float ddy = q.y - tp.y;
                    float ddz = q.z - tp.z;
                    float d2 = fmaf(ddx, ddx, fmaf(ddy, ddy, ddz * ddz));
                    unsigned long long pk =
                        ((unsigned long long)__float_as_uint(d2) << 32) |
                        (unsigned long long)__float_as_uint(tp.w);
                    if (pk < best) best = pk;
                }
            }
        }
        #pragma unroll
        for (int off = 16; off > 0; off >>= 1) {
            unsigned long long ob = __shfl_xor_sync(0xFFFFFFFFu, best, off);
            if (ob < best) best = ob;
        }
    }
    float bestd2 = __uint_as_float((unsigned int)(best >> 32));

    // ---- Phase 2: expanding rings s>=2 (rare path)
    for (int s = 2; s < G; s++) {
        float b = (float)(s - 1) * CELLH * 0.999f - o;
        if (b > 0.0f && b * b > bestd2) break;

        const int side = 2 * s + 1;
        const int box = side * side * side;
        for (int t = lane; t < box; t += 32) {
            int dz = t / (side * side);
            int rem = t - dz * side * side;
            int dy = rem / side;
            int dx = rem - dy * side;
            dz -= s; dy -= s; dx -= s;
            if (max(abs(dx), max(abs(dy), abs(dz))) != s) continue;   // shell only
            const int ix = cx + dx, iy = cy + dy, iz = cz + dz;
            if (ix < 0 || ix >= G || iy < 0 || iy >= G || iz < 0 || iz >= G) continue;
            const uint2 r = g_range[cbase + (iz * G + iy) * G + ix];
            for (unsigned int v = r.x; v < r.y; v++) {
                const float4 tp = g_sp[v];
                float ddx = q.x - tp.x;
                float ddy = q.y - tp.y;
                float ddz = q.z - tp.z;
                float d2 = fmaf(ddx, ddx, fmaf(ddy, ddy, ddz * ddz));
                unsigned long long pk =
                    ((unsigned long long)__float_as_uint(d2) << 32) |
                    (unsigned long long)__float_as_uint(tp.w);
                if (pk < best) best = pk;
            }
        }
        #pragma unroll
        for (int off = 16; off > 0; off >>= 1) {
            unsigned long long ob = __shfl_xor_sync(0xFFFFFFFFu, best, off);
            if (ob < best) best = ob;
        }
        bestd2 = __uint_as_float((unsigned int)(best >> 32));
    }

    if (lane == 0) {
        const float d = sqrtf(__uint_as_float((unsigned int)(best >> 32)));
        const unsigned int widx = (unsigned int)(best & 0xFFFFFFFFu);
        const unsigned int qorig = __float_as_uint(q.w);
        if (isB) {
            g_term[qorig] = d * __ldg(&prob[qorig]);      // s->o term
        } else {
            g_term[m + qorig] = d * __ldg(&prob[widx]);   // o->s term
        }
    }
}

// ---------------------------------------------------------------------------
// 5) deterministic fixed-order sum of n+m terms + fused final.
// ---------------------------------------------------------------------------
__global__ __launch_bounds__(256)
void reduce_kernel(int total, float* __restrict__ out) {
    __shared__ float ssum[256];
    __shared__ bool isLast;
    const int stride = gridDim.x * blockDim.x;

    float sum = 0.0f;
    for (int i = blockIdx.x * blockDim.x + threadIdx.x; i < total; i += stride)
        sum += g_term[i];

    ssum[threadIdx.x] = sum;
    __syncthreads();
    for (int off = 128; off > 0; off >>= 1) {
        if (threadIdx.x < off) ssum[threadIdx.x] += ssum[threadIdx.x + off];
        __syncthreads();
    }
    if (threadIdx.x == 0) {
        g_partials[blockIdx.x] = ssum[0];
        __threadfence();
        int t = atomicAdd(&g_done, 1);
        isLast = (t == (int)gridDim.x - 1);
    }
    __syncthreads();

    if (isLast) {
        __threadfence();
        volatile float* gp = g_partials;
        float v = (threadIdx.x < (int)gridDim.x) ? gp[threadIdx.x] : 0.0f;
        ssum[threadIdx.x] = v;
        __syncthreads();
        for (int off = 128; off > 0; off >>= 1) {
            if (threadIdx.x < off) ssum[threadIdx.x] += ssum[threadIdx.x + off];
            __syncthreads();
        }
        if (threadIdx.x == 0) {
            out[0] = ssum[0];
            g_done = 0;
        }
    }
}

// ---------------------------------------------------------------------------
// Launch: 5 kernels.
// ---------------------------------------------------------------------------
extern "C" void kernel_launch(void* const* d_in, const int* in_sizes, int n_in,
                              void* d_out, int out_size) {
    const float* P    = (const float*)d_in[0];
    const float* Ps   = (const float*)d_in[1];
    const float* prob = (const float*)d_in[2];
    float* out = (float*)d_out;

    const int n = in_sizes[0] / 3;   // 30000
    const int m = in_sizes[1] / 3;   // 10000
    const int total = n + m;
    const int nb = (total + 255) / 256;

    count_kernel<<<nb, 256>>>(P, Ps, n, m);
    scan_kernel<<<1, SCAN_T>>>();
    scatter_kernel<<<nb, 256>>>(P, Ps, n, m);
    query_kernel<<<(total * 32 + 255) / 256, 256>>>(prob, n, m);
    reduce_kernel<<<NB_RED, 256>>>(total, out);
}